// round 2
// baseline (speedup 1.0000x reference)
#include <cuda_runtime.h>
#include <cuda_bf16.h>

// EdgeGCN: 2x GCNConv (sym-norm, self loops) + edge MLP + folded scoring head.
// out[e] = sA[src] + sB[dst] + relu(ea@eW1+eb1) . v + c
//   v = eW2 @ fW[128:192],  c = eb2 . fW[128:192] + fb
//   sA[n] = h2[n] . fW[0:64], sB[n] = h2[n] . fW[64:128]
// GCN layer: m = (x@W)*dis ; s[dst] += m[src] ; agg = dis*(s+m) + b

#define NMAX 100000
#define EMAX 1600000
#define HID 64

__device__ float g_m[(size_t)NMAX * HID];   // (x@W)*dis
__device__ float g_s[(size_t)NMAX * HID];   // scatter accumulator
__device__ float g_h[(size_t)NMAX * HID];   // relu'd layer-1 output
__device__ float g_dis[NMAX];               // deg -> rsqrt(deg)
__device__ float g_sA[NMAX];
__device__ float g_sB[NMAX];
__device__ float g_v[HID];
__device__ float g_c;

// ---------------- small kernels ----------------

__global__ void k_init(int N) {
    int i = blockIdx.x * blockDim.x + threadIdx.x;
    if (i < N * HID) g_s[i] = 0.0f;
    if (i < N) g_dis[i] = 1.0f;   // self-loop contribution to degree
}

__global__ void k_deg(const int* __restrict__ dst, int E) {
    int e = blockIdx.x * blockDim.x + threadIdx.x;
    if (e < E) atomicAdd(&g_dis[dst[e]], 1.0f);
}

__global__ void k_rsqrt(int N) {
    int n = blockIdx.x * blockDim.x + threadIdx.x;
    if (n < N) g_dis[n] = rsqrtf(g_dis[n]);
}

// v[j] = sum_h eW2[j][h] * fW[128+h];  c = eb2 . fW3 + fb
__global__ void k_prep(const float* __restrict__ eW2, const float* __restrict__ eb2,
                       const float* __restrict__ fW, const float* __restrict__ fb) {
    int j = threadIdx.x;
    float acc = 0.0f;
    #pragma unroll 8
    for (int h = 0; h < HID; h++) acc += eW2[j * HID + h] * fW[128 + h];
    g_v[j] = acc;
    if (j == 0) {
        float c = fb[0];
        for (int h = 0; h < HID; h++) c += eb2[h] * fW[128 + h];
        g_c = c;
    }
}

// ---------------- GEMM1: g_m = (x[N,128] @ W1[128,64]) * dis ----------------
// 256 threads: 16 rows x (16 col-groups of 4).
__global__ __launch_bounds__(256) void k_gemm1(const float* __restrict__ x,
                                               const float* __restrict__ W, int N) {
    __shared__ float Wsh[128 * 64];
    __shared__ float xsh[16 * 128];
    int tid = threadIdx.x;
    const float4* W4 = (const float4*)W;
    float4* Wsh4 = (float4*)Wsh;
    #pragma unroll
    for (int i = 0; i < 8; i++) Wsh4[tid + i * 256] = W4[tid + i * 256];

    int nodeBase = blockIdx.x * 16;
    const float4* x4 = (const float4*)(x + (size_t)nodeBase * 128);
    float4* xsh4 = (float4*)xsh;
    #pragma unroll
    for (int i = 0; i < 2; i++) xsh4[tid + i * 256] = x4[tid + i * 256];
    __syncthreads();

    int row = tid >> 4;
    int cb = (tid & 15) * 4;
    int n = nodeBase + row;
    if (n >= N) return;
    float4 acc = make_float4(0.f, 0.f, 0.f, 0.f);
    #pragma unroll 8
    for (int k = 0; k < 128; k++) {
        float xv = xsh[row * 128 + k];
        float4 w = *(const float4*)&Wsh[k * 64 + cb];
        acc.x += xv * w.x; acc.y += xv * w.y;
        acc.z += xv * w.z; acc.w += xv * w.w;
    }
    float dis = g_dis[n];
    acc.x *= dis; acc.y *= dis; acc.z *= dis; acc.w *= dis;
    *(float4*)&g_m[(size_t)n * 64 + cb] = acc;
}

// ---------------- GEMM2: g_m = (g_h[N,64] @ W2[64,64]) * dis ----------------
__global__ __launch_bounds__(256) void k_gemm2(const float* __restrict__ W, int N) {
    __shared__ float Wsh[64 * 64];
    __shared__ float xsh[16 * 64];
    int tid = threadIdx.x;
    const float4* W4 = (const float4*)W;
    float4* Wsh4 = (float4*)Wsh;
    #pragma unroll
    for (int i = 0; i < 4; i++) Wsh4[tid + i * 256] = W4[tid + i * 256];

    int nodeBase = blockIdx.x * 16;
    const float4* x4 = (const float4*)(g_h + (size_t)nodeBase * 64);
    float4* xsh4 = (float4*)xsh;
    xsh4[tid] = x4[tid];
    __syncthreads();

    int row = tid >> 4;
    int cb = (tid & 15) * 4;
    int n = nodeBase + row;
    if (n >= N) return;
    float4 acc = make_float4(0.f, 0.f, 0.f, 0.f);
    #pragma unroll 8
    for (int k = 0; k < 64; k++) {
        float xv = xsh[row * 64 + k];
        float4 w = *(const float4*)&Wsh[k * 64 + cb];
        acc.x += xv * w.x; acc.y += xv * w.y;
        acc.z += xv * w.z; acc.w += xv * w.w;
    }
    float dis = g_dis[n];
    acc.x *= dis; acc.y *= dis; acc.z *= dis; acc.w *= dis;
    *(float4*)&g_m[(size_t)n * 64 + cb] = acc;
}

// ---------------- scatter: g_s[dst] += g_m[src], 16 threads/edge (float4) ----
__global__ __launch_bounds__(256) void k_scatter(const int* __restrict__ src,
                                                 const int* __restrict__ dst, int E) {
    int idx = blockIdx.x * blockDim.x + threadIdx.x;
    int e = idx >> 4;
    if (e >= E) return;
    int q = (idx & 15) * 4;
    int s = src[e];
    int d = dst[e];
    float4 m = *(const float4*)&g_m[(size_t)s * 64 + q];
    float* o = &g_s[(size_t)d * 64 + q];
    atomicAdd(o + 0, m.x);
    atomicAdd(o + 1, m.y);
    atomicAdd(o + 2, m.z);
    atomicAdd(o + 3, m.w);
}

// ---------------- post1: g_h = relu(dis*(g_s+g_m)+b1); re-zero g_s ----------
__global__ void k_post1(const float* __restrict__ b1, int N) {
    int i = blockIdx.x * blockDim.x + threadIdx.x;
    if (i >= N * HID) return;
    int n = i >> 6;
    int j = i & 63;
    float v = g_dis[n] * (g_s[i] + g_m[i]) + b1[j];
    g_h[i] = fmaxf(v, 0.0f);
    g_s[i] = 0.0f;
}

// ---------------- post2: sA/sB from h2 = dis*(g_s+g_m)+b2 -------------------
__global__ void k_post2(const float* __restrict__ b2, const float* __restrict__ fW, int N) {
    int gid = blockIdx.x * blockDim.x + threadIdx.x;
    int warp = gid >> 5;
    int lane = gid & 31;
    if (warp >= N) return;
    float dis = g_dis[warp];
    int i0 = warp * 64 + lane;
    int i1 = i0 + 32;
    float h0 = dis * (g_s[i0] + g_m[i0]) + b2[lane];
    float h1 = dis * (g_s[i1] + g_m[i1]) + b2[lane + 32];
    float a = h0 * fW[lane] + h1 * fW[lane + 32];
    float b = h0 * fW[64 + lane] + h1 * fW[96 + lane];
    #pragma unroll
    for (int o = 16; o; o >>= 1) {
        a += __shfl_down_sync(0xFFFFFFFFu, a, o);
        b += __shfl_down_sync(0xFFFFFFFFu, b, o);
    }
    if (lane == 0) { g_sA[warp] = a; g_sB[warp] = b; }
}

// ---------------- edge kernel: MLP + folded score + node gathers ------------
__global__ __launch_bounds__(256) void k_edge(const float* __restrict__ ea_g,
                                              const int* __restrict__ src,
                                              const int* __restrict__ dst,
                                              const float* __restrict__ eW1,
                                              const float* __restrict__ eb1,
                                              float* __restrict__ out, int E) {
    __shared__ float shW[16 * 64];
    __shared__ float shB[64];
    __shared__ float shV[64];
    int tid = threadIdx.x;
    const float4* W4 = (const float4*)eW1;
    float4* shW4 = (float4*)shW;
    shW4[tid] = W4[tid];                 // 256 float4 = 1024 floats = full eW1
    if (tid < 64) { shB[tid] = eb1[tid]; shV[tid] = g_v[tid]; }
    __syncthreads();

    int e = blockIdx.x * blockDim.x + tid;
    if (e >= E) return;

    float ea[16];
    const float4* eap = (const float4*)(ea_g + (size_t)e * 16);
    #pragma unroll
    for (int i = 0; i < 4; i++) {
        float4 t = eap[i];
        ea[i * 4 + 0] = t.x; ea[i * 4 + 1] = t.y;
        ea[i * 4 + 2] = t.z; ea[i * 4 + 3] = t.w;
    }

    float score = 0.0f;
    #pragma unroll 2
    for (int c = 0; c < 64; c += 4) {
        float4 acc = *(const float4*)&shB[c];
        #pragma unroll
        for (int k = 0; k < 16; k++) {
            float4 w = *(const float4*)&shW[k * 64 + c];
            acc.x += ea[k] * w.x; acc.y += ea[k] * w.y;
            acc.z += ea[k] * w.z; acc.w += ea[k] * w.w;
        }
        float4 vv = *(const float4*)&shV[c];
        score += fmaxf(acc.x, 0.f) * vv.x + fmaxf(acc.y, 0.f) * vv.y
               + fmaxf(acc.z, 0.f) * vv.z + fmaxf(acc.w, 0.f) * vv.w;
    }
    int s = src[e];
    int d = dst[e];
    out[e] = score + g_c + g_sA[s] + g_sB[d];
}

// ---------------- launch ----------------

extern "C" void kernel_launch(void* const* d_in, const int* in_sizes, int n_in,
                              void* d_out, int out_size) {
    const float* x        = (const float*)d_in[0];
    const int* ei         = (const int*)d_in[1];     // int32 (JAX canonicalizes int64)
    const float* ea       = (const float*)d_in[2];
    const float* W1       = (const float*)d_in[3];
    const float* b1       = (const float*)d_in[4];
    const float* W2       = (const float*)d_in[5];
    const float* b2       = (const float*)d_in[6];
    const float* eW1      = (const float*)d_in[7];
    const float* eb1      = (const float*)d_in[8];
    const float* eW2      = (const float*)d_in[9];
    const float* eb2      = (const float*)d_in[10];
    const float* fW       = (const float*)d_in[11];
    const float* fb       = (const float*)d_in[12];
    float* out            = (float*)d_out;

    int N = in_sizes[0] / 128;
    int E = in_sizes[2] / 16;
    const int* src = ei;
    const int* dst = ei + E;

    k_init<<<(N * HID + 255) / 256, 256>>>(N);
    k_deg<<<(E + 255) / 256, 256>>>(dst, E);
    k_rsqrt<<<(N + 255) / 256, 256>>>(N);
    k_prep<<<1, 64>>>(eW2, eb2, fW, fb);

    k_gemm1<<<(N + 15) / 16, 256>>>(x, W1, N);
    k_scatter<<<((long long)E * 16 + 255) / 256, 256>>>(src, dst, E);
    k_post1<<<(N * HID + 255) / 256, 256>>>(b1, N);

    k_gemm2<<<(N + 15) / 16, 256>>>(W2, N);
    k_scatter<<<((long long)E * 16 + 255) / 256, 256>>>(src, dst, E);
    k_post2<<<((long long)N * 32 + 255) / 256, 256>>>(b2, fW, N);

    k_edge<<<(E + 255) / 256, 256>>>(ea, src, dst, eW1, eb1, out, E);
}

// round 6
// speedup vs baseline: 1.7373x; 1.7373x over previous
#include <cuda_runtime.h>
#include <cuda_bf16.h>

// EdgeGCN: 2x GCNConv (sym-norm, self loops) + edge MLP + folded scoring head.
// out[e] = sA[src] + sB[dst] + relu(ea@eW1+eb1) . v + c
//   v = eW2 @ fW[128:192],  c = eb2 . fW[128:192] + fb
//   sA[n] = h2[n] . fW[0:64], sB[n] = h2[n] . fW[64:128]
// GCN layer: m = (x@W)*dis ; agg[n] = dis[n]*(sum_{src->n} m[src] + m[n]) + b
// Aggregation via unordered CSR buckets (base from atomic counter, no scan).

#define NMAX 100000
#define EMAX 1600000
#define HID 64

__device__ float g_m[(size_t)NMAX * HID];
__device__ float g_h[(size_t)NMAX * HID];
__device__ float g_dis[NMAX];
__device__ float g_sA[NMAX];
__device__ float g_sB[NMAX];
__device__ int   g_cnt[NMAX];
__device__ int   g_base[NMAX];
__device__ int   g_cur[NMAX];
__device__ int   g_srcs[EMAX];
__device__ int   g_total;
__device__ float g_v[HID];
__device__ float g_c;

// ---------------- CSR build (scan-free; bucket order irrelevant) ----------

__global__ void k_zero(int N) {
    int i = blockIdx.x * blockDim.x + threadIdx.x;
    if (i < N) g_cnt[i] = 0;
    if (i == 0) g_total = 0;
}

__global__ void k_hist(const int* __restrict__ dst, int E) {
    int e = blockIdx.x * blockDim.x + threadIdx.x;
    if (e < E) atomicAdd(&g_cnt[dst[e]], 1);
}

__global__ void k_base(int N) {
    int n = blockIdx.x * blockDim.x + threadIdx.x;
    if (n >= N) return;
    int cnt = g_cnt[n];
    int base = atomicAdd(&g_total, cnt);
    g_base[n] = base;
    g_cur[n] = base;
    g_dis[n] = rsqrtf((float)cnt + 1.0f);
}

__global__ void k_fill(const int* __restrict__ src, const int* __restrict__ dst, int E) {
    int e = blockIdx.x * blockDim.x + threadIdx.x;
    if (e >= E) return;
    int d = dst[e];
    int pos = atomicAdd(&g_cur[d], 1);
    g_srcs[pos] = src[e];
}

// ---------------- prep: v = eW2 @ fW3, c = eb2.fW3 + fb (round-2 proven) --
__global__ void k_prep(const float* __restrict__ eW2, const float* __restrict__ eb2,
                       const float* __restrict__ fW, const float* __restrict__ fb) {
    int j = threadIdx.x;
    float acc = 0.0f;
    #pragma unroll 8
    for (int h = 0; h < HID; h++) acc += eW2[j * HID + h] * fW[128 + h];
    g_v[j] = acc;
    if (j == 0) {
        float c = fb[0];
        for (int h = 0; h < HID; h++) c += eb2[h] * fW[128 + h];
        g_c = c;
    }
}

// ---------------- GEMM1 (round-2 proven): g_m = (x@W1)*dis ----------------
__global__ __launch_bounds__(256) void k_gemm1(const float* __restrict__ x,
                                               const float* __restrict__ W, int N) {
    __shared__ float Wsh[128 * 64];
    __shared__ float xsh[16 * 128];
    int tid = threadIdx.x;
    const float4* W4 = (const float4*)W;
    float4* Wsh4 = (float4*)Wsh;
    #pragma unroll
    for (int i = 0; i < 8; i++) Wsh4[tid + i * 256] = W4[tid + i * 256];

    int nodeBase = blockIdx.x * 16;
    const float4* x4 = (const float4*)(x + (size_t)nodeBase * 128);
    float4* xsh4 = (float4*)xsh;
    #pragma unroll
    for (int i = 0; i < 2; i++) xsh4[tid + i * 256] = x4[tid + i * 256];
    __syncthreads();

    int row = tid >> 4;
    int cb = (tid & 15) * 4;
    int n = nodeBase + row;
    if (n >= N) return;
    float4 acc = make_float4(0.f, 0.f, 0.f, 0.f);
    #pragma unroll 8
    for (int k = 0; k < 128; k++) {
        float xv = xsh[row * 128 + k];
        float4 w = *(const float4*)&Wsh[k * 64 + cb];
        acc.x += xv * w.x; acc.y += xv * w.y;
        acc.z += xv * w.z; acc.w += xv * w.w;
    }
    float dis = g_dis[n];
    acc.x *= dis; acc.y *= dis; acc.z *= dis; acc.w *= dis;
    *(float4*)&g_m[(size_t)n * 64 + cb] = acc;
}

// ---------------- GEMM2 (round-2 proven): g_m = (g_h@W2)*dis --------------
__global__ __launch_bounds__(256) void k_gemm2(const float* __restrict__ W, int N) {
    __shared__ float Wsh[64 * 64];
    __shared__ float xsh[16 * 64];
    int tid = threadIdx.x;
    const float4* W4 = (const float4*)W;
    float4* Wsh4 = (float4*)Wsh;
    #pragma unroll
    for (int i = 0; i < 4; i++) Wsh4[tid + i * 256] = W4[tid + i * 256];

    int nodeBase = blockIdx.x * 16;
    const float4* x4 = (const float4*)(g_h + (size_t)nodeBase * 64);
    float4* xsh4 = (float4*)xsh;
    xsh4[tid] = x4[tid];
    __syncthreads();

    int row = tid >> 4;
    int cb = (tid & 15) * 4;
    int n = nodeBase + row;
    if (n >= N) return;
    float4 acc = make_float4(0.f, 0.f, 0.f, 0.f);
    #pragma unroll 8
    for (int k = 0; k < 64; k++) {
        float xv = xsh[row * 64 + k];
        float4 w = *(const float4*)&Wsh[k * 64 + cb];
        acc.x += xv * w.x; acc.y += xv * w.y;
        acc.z += xv * w.z; acc.w += xv * w.w;
    }
    float dis = g_dis[n];
    acc.x *= dis; acc.y *= dis; acc.z *= dis; acc.w *= dis;
    *(float4*)&g_m[(size_t)n * 64 + cb] = acc;
}

// ---------------- gather layer 1: g_h = relu(dis*(sum+self)+b1) -----------
__global__ void k_gather1(const float* __restrict__ b1, int N) {
    int tid = threadIdx.x;
    int j = tid & 63;
    int n = blockIdx.x * 4 + (tid >> 6);
    if (n >= N) return;
    int s0 = g_base[n];
    int s1 = s0 + g_cnt[n];
    float acc = 0.0f;
    for (int i = s0; i < s1; i++)
        acc += g_m[(size_t)g_srcs[i] * 64 + j];
    float v = g_dis[n] * (acc + g_m[(size_t)n * 64 + j]) + b1[j];
    g_h[(size_t)n * 64 + j] = fmaxf(v, 0.0f);
}

// ---------------- gather layer 2 + folded head: sA, sB (warp per node) ----
__global__ void k_gather2(const float* __restrict__ b2,
                          const float* __restrict__ fW, int N) {
    int gid = blockIdx.x * blockDim.x + threadIdx.x;
    int warp = gid >> 5;
    int lane = gid & 31;
    if (warp >= N) return;
    int s0 = g_base[warp];
    int s1 = s0 + g_cnt[warp];
    float acc0 = 0.0f;
    float acc1 = 0.0f;
    for (int i = s0; i < s1; i++) {
        size_t r = (size_t)g_srcs[i] * 64;
        acc0 += g_m[r + lane];
        acc1 += g_m[r + lane + 32];
    }
    float dis = g_dis[warp];
    float h0 = dis * (acc0 + g_m[(size_t)warp * 64 + lane]) + b2[lane];
    float h1 = dis * (acc1 + g_m[(size_t)warp * 64 + lane + 32]) + b2[lane + 32];
    float a = h0 * fW[lane] + h1 * fW[lane + 32];
    float b = h0 * fW[64 + lane] + h1 * fW[96 + lane];
    #pragma unroll
    for (int o = 16; o; o >>= 1) {
        a += __shfl_down_sync(0xFFFFFFFFu, a, o);
        b += __shfl_down_sync(0xFFFFFFFFu, b, o);
    }
    if (lane == 0) { g_sA[warp] = a; g_sB[warp] = b; }
}

// ---------------- edge kernel (round-2 proven): 1 edge/thread -------------
__global__ __launch_bounds__(256) void k_edge(const float* __restrict__ ea_g,
                                              const int* __restrict__ src,
                                              const int* __restrict__ dst,
                                              const float* __restrict__ eW1,
                                              const float* __restrict__ eb1,
                                              float* __restrict__ out, int E) {
    __shared__ float shW[16 * 64];
    __shared__ float shB[64];
    __shared__ float shV[64];
    int tid = threadIdx.x;
    *(float4*)&shW[tid * 4] = ((const float4*)eW1)[tid];
    if (tid < 64) { shB[tid] = eb1[tid]; shV[tid] = g_v[tid]; }
    __syncthreads();

    int e = blockIdx.x * blockDim.x + tid;
    if (e >= E) return;

    float ea[16];
    const float4* eap = (const float4*)(ea_g + (size_t)e * 16);
    #pragma unroll
    for (int i = 0; i < 4; i++) {
        float4 t = eap[i];
        ea[i * 4 + 0] = t.x; ea[i * 4 + 1] = t.y;
        ea[i * 4 + 2] = t.z; ea[i * 4 + 3] = t.w;
    }

    float score = 0.0f;
    #pragma unroll 2
    for (int c = 0; c < 64; c += 4) {
        float4 acc = *(const float4*)&shB[c];
        #pragma unroll
        for (int k = 0; k < 16; k++) {
            float4 w = *(const float4*)&shW[k * 64 + c];
            acc.x += ea[k] * w.x; acc.y += ea[k] * w.y;
            acc.z += ea[k] * w.z; acc.w += ea[k] * w.w;
        }
        float4 vv = *(const float4*)&shV[c];
        score += fmaxf(acc.x, 0.f) * vv.x + fmaxf(acc.y, 0.f) * vv.y
               + fmaxf(acc.z, 0.f) * vv.z + fmaxf(acc.w, 0.f) * vv.w;
    }
    int s = src[e];
    int d = dst[e];
    out[e] = score + g_c + g_sA[s] + g_sB[d];
}

// ---------------- launch ----------------

extern "C" void kernel_launch(void* const* d_in, const int* in_sizes, int n_in,
                              void* d_out, int out_size) {
    const float* x        = (const float*)d_in[0];
    const int* ei         = (const int*)d_in[1];     // int32 (JAX canonicalizes int64)
    const float* ea       = (const float*)d_in[2];
    const float* W1       = (const float*)d_in[3];
    const float* b1       = (const float*)d_in[4];
    const float* W2       = (const float*)d_in[5];
    const float* b2       = (const float*)d_in[6];
    const float* eW1      = (const float*)d_in[7];
    const float* eb1      = (const float*)d_in[8];
    const float* eW2      = (const float*)d_in[9];
    const float* eb2      = (const float*)d_in[10];
    const float* fW       = (const float*)d_in[11];
    const float* fb       = (const float*)d_in[12];
    float* out            = (float*)d_out;

    int N = in_sizes[0] / 128;
    int E = in_sizes[2] / 16;
    const int* src = ei;
    const int* dst = ei + E;

    // CSR build (unordered buckets)
    k_zero<<<(N + 255) / 256, 256>>>(N);
    k_hist<<<(E + 255) / 256, 256>>>(dst, E);
    k_base<<<(N + 255) / 256, 256>>>(N);
    k_fill<<<(E + 255) / 256, 256>>>(src, dst, E);
    k_prep<<<1, 64>>>(eW2, eb2, fW, fb);

    // layer 1
    k_gemm1<<<(N + 15) / 16, 256>>>(x, W1, N);
    k_gather1<<<(N + 3) / 4, 256>>>(b1, N);

    // layer 2 + folded head
    k_gemm2<<<(N + 15) / 16, 256>>>(W2, N);
    k_gather2<<<((long long)N * 32 + 255) / 256, 256>>>(b2, fW, N);

    // edge MLP + score
    k_edge<<<(E + 255) / 256, 256>>>(ea, src, dst, eW1, eb1, out, E);
}

// round 7
// speedup vs baseline: 2.4972x; 1.4374x over previous
#include <cuda_runtime.h>
#include <cuda_bf16.h>

// EdgeGCN: 2x GCNConv (sym-norm, self loops) + edge MLP + folded scoring head.
// out[e] = sA[src] + sB[dst] + relu(ea@eW1+eb1) . v + c
//   v = eW2 @ fW[128:192],  c = eb2 . fW[128:192] + fb
//   sA[n] = h2[n] . fW[0:64], sB[n] = h2[n] . fW[64:128]
// GCN layer: m = (x@W)*dis ; agg[n] = dis[n]*(sum_{src->n} m[src] + m[n]) + b
// Aggregation via unordered CSR buckets (base from atomic counter, no scan).

#define NMAX 100000
#define EMAX 1600000
#define HID 64

__device__ float g_m[(size_t)NMAX * HID];
__device__ float g_h[(size_t)NMAX * HID];
__device__ float g_dis[NMAX];
__device__ float g_sA[NMAX];
__device__ float g_sB[NMAX];
__device__ int   g_cnt[NMAX];
__device__ int   g_base[NMAX];
__device__ int   g_cur[NMAX];
__device__ int   g_srcs[EMAX];
__device__ int   g_total;
__device__ float g_v[HID];
__device__ float g_c;

// ---------------- CSR build (scan-free; bucket order irrelevant) ----------

__global__ void k_zero(int N) {
    int i = blockIdx.x * blockDim.x + threadIdx.x;
    if (i < N) g_cnt[i] = 0;
    if (i == 0) g_total = 0;
}

__global__ void k_hist(const int* __restrict__ dst, int E) {
    int e = blockIdx.x * blockDim.x + threadIdx.x;
    if (e < E) atomicAdd(&g_cnt[dst[e]], 1);
}

__global__ void k_base(int N) {
    int n = blockIdx.x * blockDim.x + threadIdx.x;
    if (n >= N) return;
    int cnt = g_cnt[n];
    int base = atomicAdd(&g_total, cnt);
    g_base[n] = base;
    g_cur[n] = base;
    g_dis[n] = rsqrtf((float)cnt + 1.0f);
}

__global__ void k_fill(const int* __restrict__ src, const int* __restrict__ dst, int E) {
    int e = blockIdx.x * blockDim.x + threadIdx.x;
    if (e >= E) return;
    int d = dst[e];
    int pos = atomicAdd(&g_cur[d], 1);
    g_srcs[pos] = src[e];
}

// ---------------- prep: v = eW2 @ fW3, c = eb2.fW3 + fb -------------------
__global__ void k_prep(const float* __restrict__ eW2, const float* __restrict__ eb2,
                       const float* __restrict__ fW, const float* __restrict__ fb) {
    int j = threadIdx.x;
    float acc = 0.0f;
    #pragma unroll 8
    for (int h = 0; h < HID; h++) acc += eW2[j * HID + h] * fW[128 + h];
    g_v[j] = acc;
    if (j == 0) {
        float c = fb[0];
        for (int h = 0; h < HID; h++) c += eb2[h] * fW[128 + h];
        g_c = c;
    }
}

// ---------------- GEMM1: g_m = (x[N,128] @ W1[128,64]) * dis --------------
// 64-row x 64-col tile, 256 threads, each 4 rows x 4 cols; k tiled by 64.
__global__ __launch_bounds__(256) void k_gemm1(const float* __restrict__ x,
                                               const float* __restrict__ W, int N) {
    __shared__ float Wsh[64 * 64];
    __shared__ float xsh[64 * 65];
    int tid = threadIdx.x;
    int rg = tid >> 4;        // 0..15 -> rows rg*4..rg*4+3
    int cg = tid & 15;        // cols cg*4
    int base = blockIdx.x * 64;

    float4 a0 = make_float4(0.f, 0.f, 0.f, 0.f);
    float4 a1 = a0, a2 = a0, a3 = a0;

    const float4* x4 = (const float4*)x;   // 32 float4 per row
    const float4* W4 = (const float4*)W;   // 16 float4 per row

    for (int kt = 0; kt < 2; kt++) {
        __syncthreads();
        // W slice: k rows kt*64..+63, 64x64 = 1024 float4
        #pragma unroll
        for (int i = 0; i < 4; i++) {
            int idx = tid + i * 256;
            int kk = idx >> 4;
            int cq = idx & 15;
            *(float4*)&Wsh[kk * 64 + cq * 4] = W4[(size_t)(kt * 64 + kk) * 16 + cq];
        }
        // x slice: 64 rows x 64 k, padded stride 65
        #pragma unroll
        for (int i = 0; i < 4; i++) {
            int idx = tid + i * 256;
            int row = idx >> 4;
            int kq = idx & 15;
            int n = base + row;
            float4 v = make_float4(0.f, 0.f, 0.f, 0.f);
            if (n < N) v = x4[(size_t)n * 32 + kt * 16 + kq];
            float* p = &xsh[row * 65 + kq * 4];
            p[0] = v.x; p[1] = v.y; p[2] = v.z; p[3] = v.w;
        }
        __syncthreads();

        #pragma unroll 16
        for (int k = 0; k < 64; k++) {
            float4 w = *(const float4*)&Wsh[k * 64 + cg * 4];
            float x0 = xsh[(rg * 4 + 0) * 65 + k];
            float x1 = xsh[(rg * 4 + 1) * 65 + k];
            float x2 = xsh[(rg * 4 + 2) * 65 + k];
            float x3 = xsh[(rg * 4 + 3) * 65 + k];
            a0.x += x0 * w.x; a0.y += x0 * w.y; a0.z += x0 * w.z; a0.w += x0 * w.w;
            a1.x += x1 * w.x; a1.y += x1 * w.y; a1.z += x1 * w.z; a1.w += x1 * w.w;
            a2.x += x2 * w.x; a2.y += x2 * w.y; a2.z += x2 * w.z; a2.w += x2 * w.w;
            a3.x += x3 * w.x; a3.y += x3 * w.y; a3.z += x3 * w.z; a3.w += x3 * w.w;
        }
    }

    int n0 = base + rg * 4;
    if (n0 + 0 < N) { float d = g_dis[n0 + 0];
        *(float4*)&g_m[(size_t)(n0 + 0) * 64 + cg * 4] = make_float4(a0.x * d, a0.y * d, a0.z * d, a0.w * d); }
    if (n0 + 1 < N) { float d = g_dis[n0 + 1];
        *(float4*)&g_m[(size_t)(n0 + 1) * 64 + cg * 4] = make_float4(a1.x * d, a1.y * d, a1.z * d, a1.w * d); }
    if (n0 + 2 < N) { float d = g_dis[n0 + 2];
        *(float4*)&g_m[(size_t)(n0 + 2) * 64 + cg * 4] = make_float4(a2.x * d, a2.y * d, a2.z * d, a2.w * d); }
    if (n0 + 3 < N) { float d = g_dis[n0 + 3];
        *(float4*)&g_m[(size_t)(n0 + 3) * 64 + cg * 4] = make_float4(a3.x * d, a3.y * d, a3.z * d, a3.w * d); }
}

// ---------------- GEMM2: g_m = (g_h[N,64] @ W2[64,64]) * dis --------------
__global__ __launch_bounds__(256) void k_gemm2(const float* __restrict__ W, int N) {
    __shared__ float Wsh[64 * 64];
    __shared__ float xsh[64 * 65];
    int tid = threadIdx.x;
    int rg = tid >> 4;
    int cg = tid & 15;
    int base = blockIdx.x * 64;

    float4 a0 = make_float4(0.f, 0.f, 0.f, 0.f);
    float4 a1 = a0, a2 = a0, a3 = a0;

    const float4* x4 = (const float4*)g_h;  // 16 float4 per row
    const float4* W4 = (const float4*)W;

    #pragma unroll
    for (int i = 0; i < 4; i++) {
        int idx = tid + i * 256;
        int kk = idx >> 4;
        int cq = idx & 15;
        *(float4*)&Wsh[kk * 64 + cq * 4] = W4[(size_t)kk * 16 + cq];
    }
    #pragma unroll
    for (int i = 0; i < 4; i++) {
        int idx = tid + i * 256;
        int row = idx >> 4;
        int kq = idx & 15;
        int n = base + row;
        float4 v = make_float4(0.f, 0.f, 0.f, 0.f);
        if (n < N) v = x4[(size_t)n * 16 + kq];
        float* p = &xsh[row * 65 + kq * 4];
        p[0] = v.x; p[1] = v.y; p[2] = v.z; p[3] = v.w;
    }
    __syncthreads();

    #pragma unroll 16
    for (int k = 0; k < 64; k++) {
        float4 w = *(const float4*)&Wsh[k * 64 + cg * 4];
        float x0 = xsh[(rg * 4 + 0) * 65 + k];
        float x1 = xsh[(rg * 4 + 1) * 65 + k];
        float x2 = xsh[(rg * 4 + 2) * 65 + k];
        float x3 = xsh[(rg * 4 + 3) * 65 + k];
        a0.x += x0 * w.x; a0.y += x0 * w.y; a0.z += x0 * w.z; a0.w += x0 * w.w;
        a1.x += x1 * w.x; a1.y += x1 * w.y; a1.z += x1 * w.z; a1.w += x1 * w.w;
        a2.x += x2 * w.x; a2.y += x2 * w.y; a2.z += x2 * w.z; a2.w += x2 * w.w;
        a3.x += x3 * w.x; a3.y += x3 * w.y; a3.z += x3 * w.z; a3.w += x3 * w.w;
    }

    int n0 = base + rg * 4;
    if (n0 + 0 < N) { float d = g_dis[n0 + 0];
        *(float4*)&g_m[(size_t)(n0 + 0) * 64 + cg * 4] = make_float4(a0.x * d, a0.y * d, a0.z * d, a0.w * d); }
    if (n0 + 1 < N) { float d = g_dis[n0 + 1];
        *(float4*)&g_m[(size_t)(n0 + 1) * 64 + cg * 4] = make_float4(a1.x * d, a1.y * d, a1.z * d, a1.w * d); }
    if (n0 + 2 < N) { float d = g_dis[n0 + 2];
        *(float4*)&g_m[(size_t)(n0 + 2) * 64 + cg * 4] = make_float4(a2.x * d, a2.y * d, a2.z * d, a2.w * d); }
    if (n0 + 3 < N) { float d = g_dis[n0 + 3];
        *(float4*)&g_m[(size_t)(n0 + 3) * 64 + cg * 4] = make_float4(a3.x * d, a3.y * d, a3.z * d, a3.w * d); }
}

// ---------------- gather layer 1: g_h = relu(dis*(sum+self)+b1) -----------
__global__ void k_gather1(const float* __restrict__ b1, int N) {
    int tid = threadIdx.x;
    int j = tid & 63;
    int n = blockIdx.x * 4 + (tid >> 6);
    if (n >= N) return;
    int s0 = g_base[n];
    int s1 = s0 + g_cnt[n];
    float acc = 0.0f;
    for (int i = s0; i < s1; i++)
        acc += g_m[(size_t)g_srcs[i] * 64 + j];
    float v = g_dis[n] * (acc + g_m[(size_t)n * 64 + j]) + b1[j];
    g_h[(size_t)n * 64 + j] = fmaxf(v, 0.0f);
}

// ---------------- gather layer 2 + folded head: sA, sB (warp per node) ----
__global__ void k_gather2(const float* __restrict__ b2,
                          const float* __restrict__ fW, int N) {
    int gid = blockIdx.x * blockDim.x + threadIdx.x;
    int warp = gid >> 5;
    int lane = gid & 31;
    if (warp >= N) return;
    int s0 = g_base[warp];
    int s1 = s0 + g_cnt[warp];
    float acc0 = 0.0f;
    float acc1 = 0.0f;
    for (int i = s0; i < s1; i++) {
        size_t r = (size_t)g_srcs[i] * 64;
        acc0 += g_m[r + lane];
        acc1 += g_m[r + lane + 32];
    }
    float dis = g_dis[warp];
    float h0 = dis * (acc0 + g_m[(size_t)warp * 64 + lane]) + b2[lane];
    float h1 = dis * (acc1 + g_m[(size_t)warp * 64 + lane + 32]) + b2[lane + 32];
    float a = h0 * fW[lane] + h1 * fW[lane + 32];
    float b = h0 * fW[64 + lane] + h1 * fW[96 + lane];
    #pragma unroll
    for (int o = 16; o; o >>= 1) {
        a += __shfl_down_sync(0xFFFFFFFFu, a, o);
        b += __shfl_down_sync(0xFFFFFFFFu, b, o);
    }
    if (lane == 0) { g_sA[warp] = a; g_sB[warp] = b; }
}

// ---------------- edge kernel: 2 edges/thread, scalar FMAs ----------------
__global__ __launch_bounds__(256) void k_edge(const float* __restrict__ ea_g,
                                              const int* __restrict__ src,
                                              const int* __restrict__ dst,
                                              const float* __restrict__ eW1,
                                              const float* __restrict__ eb1,
                                              float* __restrict__ out, int E) {
    __shared__ float shW[16 * 64];
    __shared__ float shB[64];
    __shared__ float shV[64];
    int tid = threadIdx.x;
    *(float4*)&shW[tid * 4] = ((const float4*)eW1)[tid];
    if (tid < 64) { shB[tid] = eb1[tid]; shV[tid] = g_v[tid]; }
    __syncthreads();

    int e0 = blockIdx.x * 512 + tid;
    int e1 = e0 + 256;
    bool ok0 = e0 < E;
    bool ok1 = e1 < E;

    float ea0[16];
    float ea1[16];
    const float4* p0 = (const float4*)(ea_g + (size_t)e0 * 16);
    const float4* p1 = (const float4*)(ea_g + (size_t)e1 * 16);
    #pragma unroll
    for (int i = 0; i < 4; i++) {
        float4 t = ok0 ? p0[i] : make_float4(0.f, 0.f, 0.f, 0.f);
        ea0[i * 4 + 0] = t.x; ea0[i * 4 + 1] = t.y;
        ea0[i * 4 + 2] = t.z; ea0[i * 4 + 3] = t.w;
    }
    #pragma unroll
    for (int i = 0; i < 4; i++) {
        float4 t = ok1 ? p1[i] : make_float4(0.f, 0.f, 0.f, 0.f);
        ea1[i * 4 + 0] = t.x; ea1[i * 4 + 1] = t.y;
        ea1[i * 4 + 2] = t.z; ea1[i * 4 + 3] = t.w;
    }

    float score0 = 0.0f;
    float score1 = 0.0f;
    #pragma unroll 2
    for (int c = 0; c < 64; c += 4) {
        float4 accA = *(const float4*)&shB[c];
        float4 accB = accA;
        #pragma unroll
        for (int k = 0; k < 16; k++) {
            float4 w = *(const float4*)&shW[k * 64 + c];
            accA.x += ea0[k] * w.x; accA.y += ea0[k] * w.y;
            accA.z += ea0[k] * w.z; accA.w += ea0[k] * w.w;
            accB.x += ea1[k] * w.x; accB.y += ea1[k] * w.y;
            accB.z += ea1[k] * w.z; accB.w += ea1[k] * w.w;
        }
        float4 vv = *(const float4*)&shV[c];
        score0 += fmaxf(accA.x, 0.f) * vv.x + fmaxf(accA.y, 0.f) * vv.y
                + fmaxf(accA.z, 0.f) * vv.z + fmaxf(accA.w, 0.f) * vv.w;
        score1 += fmaxf(accB.x, 0.f) * vv.x + fmaxf(accB.y, 0.f) * vv.y
                + fmaxf(accB.z, 0.f) * vv.z + fmaxf(accB.w, 0.f) * vv.w;
    }

    float c0 = g_c;
    if (ok0) out[e0] = score0 + c0 + g_sA[src[e0]] + g_sB[dst[e0]];
    if (ok1) out[e1] = score1 + c0 + g_sA[src[e1]] + g_sB[dst[e1]];
}

// ---------------- launch ----------------

extern "C" void kernel_launch(void* const* d_in, const int* in_sizes, int n_in,
                              void* d_out, int out_size) {
    const float* x        = (const float*)d_in[0];
    const int* ei         = (const int*)d_in[1];     // int32 (JAX canonicalizes int64)
    const float* ea       = (const float*)d_in[2];
    const float* W1       = (const float*)d_in[3];
    const float* b1       = (const float*)d_in[4];
    const float* W2       = (const float*)d_in[5];
    const float* b2       = (const float*)d_in[6];
    const float* eW1      = (const float*)d_in[7];
    const float* eb1      = (const float*)d_in[8];
    const float* eW2      = (const float*)d_in[9];
    const float* eb2      = (const float*)d_in[10];
    const float* fW       = (const float*)d_in[11];
    const float* fb       = (const float*)d_in[12];
    float* out            = (float*)d_out;

    int N = in_sizes[0] / 128;
    int E = in_sizes[2] / 16;
    const int* src = ei;
    const int* dst = ei + E;

    // CSR build (unordered buckets)
    k_zero<<<(N + 255) / 256, 256>>>(N);
    k_hist<<<(E + 255) / 256, 256>>>(dst, E);
    k_base<<<(N + 255) / 256, 256>>>(N);
    k_fill<<<(E + 255) / 256, 256>>>(src, dst, E);
    k_prep<<<1, 64>>>(eW2, eb2, fW, fb);

    // layer 1
    k_gemm1<<<(N + 63) / 64, 256>>>(x, W1, N);
    k_gather1<<<(N + 3) / 4, 256>>>(b1, N);

    // layer 2 + folded head
    k_gemm2<<<(N + 63) / 64, 256>>>(W2, N);
    k_gather2<<<((long long)N * 32 + 255) / 256, 256>>>(b2, fW, N);

    // edge MLP + score
    k_edge<<<(E + 511) / 512, 256>>>(ea, src, dst, eW1, eb1, out, E);
}

// round 8
// speedup vs baseline: 2.9634x; 1.1867x over previous
#include <cuda_runtime.h>
#include <cuda_bf16.h>

// EdgeGCN: 2x GCNConv (sym-norm, self loops) + edge MLP + folded scoring head.
// out[e] = sA[src] + sB[dst] + relu(ea@eW1+eb1) . v + c
//   v = eW2 @ fW[128:192],  c = eb2 . fW[128:192] + fb
// Layer-2 is fully folded (linear):
//   uA = W2 @ fW[0:64], uB = W2 @ fW[64:128]
//   tA[n] = dis[n]*(h[n].uA), tB[n] = dis[n]*(h[n].uB)
//   sA[n] = dis[n]*(sum_{src->n} tA[src] + tA[n]) + b2.fW[0:64]   (sB analogous)
// Layer-1: m = (x@W1)*dis ; h = relu(dis*(sum+self)+b1)
// Aggregation via fixed-capacity buckets (no histogram/scan, no float atomics).

#define NMAX 100000
#define EMAX 1600000
#define HID 64
#define CAP 128   // bucket capacity per node (Poisson(16) in-degree; 128 is >> max)

__device__ float  g_m[(size_t)NMAX * HID];
__device__ float  g_h[(size_t)NMAX * HID];
__device__ float  g_dis[NMAX];
__device__ float  g_sA[NMAX];
__device__ float  g_sB[NMAX];
__device__ float2 g_tab[NMAX];
__device__ int    g_cnt[NMAX];
__device__ int    g_srcs[(size_t)NMAX * CAP];
__device__ float  g_v[HID];
__device__ float  g_uA[HID];
__device__ float  g_uB[HID];
__device__ float  g_c;
__device__ float  g_cA;
__device__ float  g_cB;

// ---------------- bucket build ----------------

__global__ void k_zero(int N) {
    int i = blockIdx.x * blockDim.x + threadIdx.x;
    if (i < N) g_cnt[i] = 0;
}

__global__ void k_fill(const int* __restrict__ src, const int* __restrict__ dst, int E) {
    int e = blockIdx.x * blockDim.x + threadIdx.x;
    if (e >= E) return;
    int d = dst[e];
    int pos = atomicAdd(&g_cnt[d], 1);
    if (pos < CAP) g_srcs[(size_t)d * CAP + pos] = src[e];
}

__global__ void k_dis(int N) {
    int n = blockIdx.x * blockDim.x + threadIdx.x;
    if (n < N) g_dis[n] = rsqrtf((float)g_cnt[n] + 1.0f);
}

// ---------------- prep: v, uA, uB, constants ----------------
// 192 threads: [0,64) v[j]; [64,128) uA[k]; [128,192) uB[k]
__global__ void k_prep(const float* __restrict__ eW2, const float* __restrict__ eb2,
                       const float* __restrict__ W2, const float* __restrict__ b2,
                       const float* __restrict__ fW, const float* __restrict__ fb) {
    int tid = threadIdx.x;
    if (tid < 64) {
        float acc = 0.0f;
        for (int h = 0; h < HID; h++) acc += eW2[tid * HID + h] * fW[128 + h];
        g_v[tid] = acc;
    } else if (tid < 128) {
        int k = tid - 64;
        float acc = 0.0f;
        for (int j = 0; j < HID; j++) acc += W2[k * HID + j] * fW[j];
        g_uA[k] = acc;
    } else {
        int k = tid - 128;
        float acc = 0.0f;
        for (int j = 0; j < HID; j++) acc += W2[k * HID + j] * fW[64 + j];
        g_uB[k] = acc;
    }
    if (tid == 0) {
        float c = fb[0], ca = 0.0f, cb = 0.0f;
        for (int h = 0; h < HID; h++) {
            c  += eb2[h] * fW[128 + h];
            ca += b2[h] * fW[h];
            cb += b2[h] * fW[64 + h];
        }
        g_c = c; g_cA = ca; g_cB = cb;
    }
}

// ---------------- GEMM1: g_m = (x[N,128] @ W1[128,64]) * dis --------------
// 64-row x 64-col tile, 256 threads, each 4 rows x 4 cols; k tiled by 64.
__global__ __launch_bounds__(256) void k_gemm1(const float* __restrict__ x,
                                               const float* __restrict__ W, int N) {
    __shared__ float Wsh[64 * 64];
    __shared__ float xsh[64 * 65];
    int tid = threadIdx.x;
    int rg = tid >> 4;
    int cg = tid & 15;
    int base = blockIdx.x * 64;

    float4 a0 = make_float4(0.f, 0.f, 0.f, 0.f);
    float4 a1 = a0, a2 = a0, a3 = a0;

    const float4* x4 = (const float4*)x;
    const float4* W4 = (const float4*)W;

    for (int kt = 0; kt < 2; kt++) {
        __syncthreads();
        #pragma unroll
        for (int i = 0; i < 4; i++) {
            int idx = tid + i * 256;
            int kk = idx >> 4;
            int cq = idx & 15;
            *(float4*)&Wsh[kk * 64 + cq * 4] = W4[(size_t)(kt * 64 + kk) * 16 + cq];
        }
        #pragma unroll
        for (int i = 0; i < 4; i++) {
            int idx = tid + i * 256;
            int row = idx >> 4;
            int kq = idx & 15;
            int n = base + row;
            float4 v = make_float4(0.f, 0.f, 0.f, 0.f);
            if (n < N) v = x4[(size_t)n * 32 + kt * 16 + kq];
            float* p = &xsh[row * 65 + kq * 4];
            p[0] = v.x; p[1] = v.y; p[2] = v.z; p[3] = v.w;
        }
        __syncthreads();

        #pragma unroll 16
        for (int k = 0; k < 64; k++) {
            float4 w = *(const float4*)&Wsh[k * 64 + cg * 4];
            float x0 = xsh[(rg * 4 + 0) * 65 + k];
            float x1 = xsh[(rg * 4 + 1) * 65 + k];
            float x2 = xsh[(rg * 4 + 2) * 65 + k];
            float x3 = xsh[(rg * 4 + 3) * 65 + k];
            a0.x += x0 * w.x; a0.y += x0 * w.y; a0.z += x0 * w.z; a0.w += x0 * w.w;
            a1.x += x1 * w.x; a1.y += x1 * w.y; a1.z += x1 * w.z; a1.w += x1 * w.w;
            a2.x += x2 * w.x; a2.y += x2 * w.y; a2.z += x2 * w.z; a2.w += x2 * w.w;
            a3.x += x3 * w.x; a3.y += x3 * w.y; a3.z += x3 * w.z; a3.w += x3 * w.w;
        }
    }

    int n0 = base + rg * 4;
    if (n0 + 0 < N) { float d = g_dis[n0 + 0];
        *(float4*)&g_m[(size_t)(n0 + 0) * 64 + cg * 4] = make_float4(a0.x * d, a0.y * d, a0.z * d, a0.w * d); }
    if (n0 + 1 < N) { float d = g_dis[n0 + 1];
        *(float4*)&g_m[(size_t)(n0 + 1) * 64 + cg * 4] = make_float4(a1.x * d, a1.y * d, a1.z * d, a1.w * d); }
    if (n0 + 2 < N) { float d = g_dis[n0 + 2];
        *(float4*)&g_m[(size_t)(n0 + 2) * 64 + cg * 4] = make_float4(a2.x * d, a2.y * d, a2.z * d, a2.w * d); }
    if (n0 + 3 < N) { float d = g_dis[n0 + 3];
        *(float4*)&g_m[(size_t)(n0 + 3) * 64 + cg * 4] = make_float4(a3.x * d, a3.y * d, a3.z * d, a3.w * d); }
}

// ---------------- gather layer 1: g_h = relu(dis*(sum+self)+b1) -----------
__global__ void k_gather1(const float* __restrict__ b1, int N) {
    int tid = threadIdx.x;
    int j = tid & 63;
    int n = blockIdx.x * 4 + (tid >> 6);
    if (n >= N) return;
    size_t s0 = (size_t)n * CAP;
    size_t s1 = s0 + g_cnt[n];
    float acc = 0.0f;
    for (size_t i = s0; i < s1; i++)
        acc += g_m[(size_t)g_srcs[i] * 64 + j];
    float v = g_dis[n] * (acc + g_m[(size_t)n * 64 + j]) + b1[j];
    g_h[(size_t)n * 64 + j] = fmaxf(v, 0.0f);
}

// ---------------- tab: tA = dis*(h.uA), tB = dis*(h.uB); warp per node ----
__global__ void k_tab(int N) {
    int gid = blockIdx.x * blockDim.x + threadIdx.x;
    int warp = gid >> 5;
    int lane = gid & 31;
    if (warp >= N) return;
    float h0 = g_h[(size_t)warp * 64 + lane];
    float h1 = g_h[(size_t)warp * 64 + lane + 32];
    float a = h0 * g_uA[lane] + h1 * g_uA[lane + 32];
    float b = h0 * g_uB[lane] + h1 * g_uB[lane + 32];
    #pragma unroll
    for (int o = 16; o; o >>= 1) {
        a += __shfl_down_sync(0xFFFFFFFFu, a, o);
        b += __shfl_down_sync(0xFFFFFFFFu, b, o);
    }
    if (lane == 0) {
        float dis = g_dis[warp];
        g_tab[warp] = make_float2(a * dis, b * dis);
    }
}

// ---------------- scalar gather 2: sA, sB; thread per node ----------------
__global__ void k_gather2s(int N) {
    int n = blockIdx.x * blockDim.x + threadIdx.x;
    if (n >= N) return;
    size_t s0 = (size_t)n * CAP;
    size_t s1 = s0 + g_cnt[n];
    float2 self = g_tab[n];
    float a = self.x, b = self.y;
    for (size_t i = s0; i < s1; i++) {
        float2 t = g_tab[g_srcs[i]];
        a += t.x; b += t.y;
    }
    float dis = g_dis[n];
    g_sA[n] = dis * a + g_cA;
    g_sB[n] = dis * b + g_cB;
}

// ---------------- edge kernel: 2 edges/thread, scalar FMAs ----------------
__global__ __launch_bounds__(256) void k_edge(const float* __restrict__ ea_g,
                                              const int* __restrict__ src,
                                              const int* __restrict__ dst,
                                              const float* __restrict__ eW1,
                                              const float* __restrict__ eb1,
                                              float* __restrict__ out, int E) {
    __shared__ float shW[16 * 64];
    __shared__ float shB[64];
    __shared__ float shV[64];
    int tid = threadIdx.x;
    *(float4*)&shW[tid * 4] = ((const float4*)eW1)[tid];
    if (tid < 64) { shB[tid] = eb1[tid]; shV[tid] = g_v[tid]; }
    __syncthreads();

    int e0 = blockIdx.x * 512 + tid;
    int e1 = e0 + 256;
    bool ok0 = e0 < E;
    bool ok1 = e1 < E;

    float ea0[16];
    float ea1[16];
    const float4* p0 = (const float4*)(ea_g + (size_t)e0 * 16);
    const float4* p1 = (const float4*)(ea_g + (size_t)e1 * 16);
    #pragma unroll
    for (int i = 0; i < 4; i++) {
        float4 t = ok0 ? p0[i] : make_float4(0.f, 0.f, 0.f, 0.f);
        ea0[i * 4 + 0] = t.x; ea0[i * 4 + 1] = t.y;
        ea0[i * 4 + 2] = t.z; ea0[i * 4 + 3] = t.w;
    }
    #pragma unroll
    for (int i = 0; i < 4; i++) {
        float4 t = ok1 ? p1[i] : make_float4(0.f, 0.f, 0.f, 0.f);
        ea1[i * 4 + 0] = t.x; ea1[i * 4 + 1] = t.y;
        ea1[i * 4 + 2] = t.z; ea1[i * 4 + 3] = t.w;
    }

    float score0 = 0.0f;
    float score1 = 0.0f;
    #pragma unroll 2
    for (int c = 0; c < 64; c += 4) {
        float4 accA = *(const float4*)&shB[c];
        float4 accB = accA;
        #pragma unroll
        for (int k = 0; k < 16; k++) {
            float4 w = *(const float4*)&shW[k * 64 + c];
            accA.x += ea0[k] * w.x; accA.y += ea0[k] * w.y;
            accA.z += ea0[k] * w.z; accA.w += ea0[k] * w.w;
            accB.x += ea1[k] * w.x; accB.y += ea1[k] * w.y;
            accB.z += ea1[k] * w.z; accB.w += ea1[k] * w.w;
        }
        float4 vv = *(const float4*)&shV[c];
        score0 += fmaxf(accA.x, 0.f) * vv.x + fmaxf(accA.y, 0.f) * vv.y
                + fmaxf(accA.z, 0.f) * vv.z + fmaxf(accA.w, 0.f) * vv.w;
        score1 += fmaxf(accB.x, 0.f) * vv.x + fmaxf(accB.y, 0.f) * vv.y
                + fmaxf(accB.z, 0.f) * vv.z + fmaxf(accB.w, 0.f) * vv.w;
    }

    float c0 = g_c;
    if (ok0) out[e0] = score0 + c0 + g_sA[src[e0]] + g_sB[dst[e0]];
    if (ok1) out[e1] = score1 + c0 + g_sA[src[e1]] + g_sB[dst[e1]];
}

// ---------------- launch ----------------

extern "C" void kernel_launch(void* const* d_in, const int* in_sizes, int n_in,
                              void* d_out, int out_size) {
    const float* x        = (const float*)d_in[0];
    const int* ei         = (const int*)d_in[1];     // int32 (JAX canonicalizes int64)
    const float* ea       = (const float*)d_in[2];
    const float* W1       = (const float*)d_in[3];
    const float* b1       = (const float*)d_in[4];
    const float* W2       = (const float*)d_in[5];
    const float* b2       = (const float*)d_in[6];
    const float* eW1      = (const float*)d_in[7];
    const float* eb1      = (const float*)d_in[8];
    const float* eW2      = (const float*)d_in[9];
    const float* eb2      = (const float*)d_in[10];
    const float* fW       = (const float*)d_in[11];
    const float* fb       = (const float*)d_in[12];
    float* out            = (float*)d_out;

    int N = in_sizes[0] / 128;
    int E = in_sizes[2] / 16;
    const int* src = ei;
    const int* dst = ei + E;

    // bucket build
    k_zero<<<(N + 255) / 256, 256>>>(N);
    k_fill<<<(E + 255) / 256, 256>>>(src, dst, E);
    k_dis<<<(N + 255) / 256, 256>>>(N);
    k_prep<<<1, 192>>>(eW2, eb2, W2, b2, fW, fb);

    // layer 1
    k_gemm1<<<(N + 63) / 64, 256>>>(x, W1, N);
    k_gather1<<<(N + 3) / 4, 256>>>(b1, N);

    // layer 2 (folded): per-node scalars + scalar gather
    k_tab<<<((long long)N * 32 + 255) / 256, 256>>>(N);
    k_gather2s<<<(N + 255) / 256, 256>>>(N);

    // edge MLP + score
    k_edge<<<(E + 511) / 512, 256>>>(ea, src, dst, eW1, eb1, out, E);
}

// round 9
// speedup vs baseline: 3.1720x; 1.0704x over previous
#include <cuda_runtime.h>
#include <cuda_bf16.h>

// EdgeGCN: 2x GCNConv (sym-norm, self loops) + edge MLP + folded scoring head.
// out[e] = sA[src] + sB[dst] + relu(ea@eW1+eb1) . v + c
//   v = eW2 @ fW[128:192],  c = eb2 . fW[128:192] + fb
// Layer-2 fully folded (linear):
//   uA = W2 @ fW[0:64], uB = W2 @ fW[64:128]
//   tA[n] = dis[n]*(h[n].uA), tB[n] = dis[n]*(h[n].uB)
//   sA[n] = dis[n]*(sum_{src->n} tA[src] + tA[n]) + b2.fW[0:64]   (sB analogous)
// Layer-1: m = (x@W1)*dis ; h = relu(dis*(sum+self)+b1)
// Aggregation via fixed-capacity buckets (no histogram/scan, no float atomics).

#define NMAX 100000
#define EMAX 1600000
#define HID 64
#define CAP 128   // bucket capacity per node (Poisson(16) in-degree; 128 is >> max)

__device__ float  g_m[(size_t)NMAX * HID];
__device__ float  g_h[(size_t)NMAX * HID];
__device__ float  g_dis[NMAX];
__device__ float  g_sA[NMAX];
__device__ float  g_sB[NMAX];
__device__ float2 g_tab[NMAX];
__device__ int    g_cnt[NMAX];
__device__ int    g_srcs[(size_t)NMAX * CAP];
__device__ float  g_v[HID];
__device__ float  g_uA[HID];
__device__ float  g_uB[HID];
__device__ float  g_c;
__device__ float  g_cA;
__device__ float  g_cB;

typedef unsigned long long ull;

__device__ __forceinline__ ull pack2(float x) {
    ull r; asm("mov.b64 %0, {%1, %1};" : "=l"(r) : "f"(x)); return r;
}
__device__ __forceinline__ ull fma2(ull a, ull b, ull c) {
    ull d; asm("fma.rn.f32x2 %0, %1, %2, %3;" : "=l"(d) : "l"(a), "l"(b), "l"(c)); return d;
}
__device__ __forceinline__ void unpack2(ull v, float& lo, float& hi) {
    asm("mov.b64 {%0, %1}, %2;" : "=f"(lo), "=f"(hi) : "l"(v));
}

// ---------------- bucket build ----------------

__global__ void k_zero(int N) {
    int i = blockIdx.x * blockDim.x + threadIdx.x;
    if (i < N) g_cnt[i] = 0;
}

__global__ void k_fill(const int* __restrict__ src, const int* __restrict__ dst, int E) {
    int e = blockIdx.x * blockDim.x + threadIdx.x;
    if (e >= E) return;
    int d = dst[e];
    int pos = atomicAdd(&g_cnt[d], 1);
    if (pos < CAP) g_srcs[(size_t)d * CAP + pos] = src[e];
}

__global__ void k_dis(int N) {
    int n = blockIdx.x * blockDim.x + threadIdx.x;
    if (n < N) g_dis[n] = rsqrtf((float)g_cnt[n] + 1.0f);
}

// ---------------- prep: warp per output scalar -----------------------------
// warps 0..63: v[j]; 64..127: uA; 128..191: uB; 192: c; 193: cA; 194: cB
__global__ __launch_bounds__(256) void k_prep(const float* __restrict__ eW2,
                                              const float* __restrict__ eb2,
                                              const float* __restrict__ W2,
                                              const float* __restrict__ b2,
                                              const float* __restrict__ fW,
                                              const float* __restrict__ fb) {
    int gid = blockIdx.x * blockDim.x + threadIdx.x;
    int w = gid >> 5;
    int l = gid & 31;
    float acc = 0.0f;
    if (w < 64) {
        acc = eW2[w * HID + l] * fW[128 + l] + eW2[w * HID + l + 32] * fW[160 + l];
    } else if (w < 128) {
        int k = w - 64;
        acc = W2[k * HID + l] * fW[l] + W2[k * HID + l + 32] * fW[l + 32];
    } else if (w < 192) {
        int k = w - 128;
        acc = W2[k * HID + l] * fW[64 + l] + W2[k * HID + l + 32] * fW[96 + l];
    } else if (w == 192) {
        acc = eb2[l] * fW[128 + l] + eb2[l + 32] * fW[160 + l];
    } else if (w == 193) {
        acc = b2[l] * fW[l] + b2[l + 32] * fW[l + 32];
    } else if (w == 194) {
        acc = b2[l] * fW[64 + l] + b2[l + 32] * fW[96 + l];
    } else return;
    #pragma unroll
    for (int o = 16; o; o >>= 1) acc += __shfl_down_sync(0xFFFFFFFFu, acc, o);
    if (l == 0) {
        if (w < 64) g_v[w] = acc;
        else if (w < 128) g_uA[w - 64] = acc;
        else if (w < 192) g_uB[w - 128] = acc;
        else if (w == 192) g_c = acc + fb[0];
        else if (w == 193) g_cA = acc;
        else g_cB = acc;
    }
}

// ---------------- GEMM1: g_m = (x[N,128] @ W1[128,64]) * dis --------------
__global__ __launch_bounds__(256) void k_gemm1(const float* __restrict__ x,
                                               const float* __restrict__ W, int N) {
    __shared__ float Wsh[64 * 64];
    __shared__ float xsh[64 * 65];
    int tid = threadIdx.x;
    int rg = tid >> 4;
    int cg = tid & 15;
    int base = blockIdx.x * 64;

    float4 a0 = make_float4(0.f, 0.f, 0.f, 0.f);
    float4 a1 = a0, a2 = a0, a3 = a0;

    const float4* x4 = (const float4*)x;
    const float4* W4 = (const float4*)W;

    for (int kt = 0; kt < 2; kt++) {
        __syncthreads();
        #pragma unroll
        for (int i = 0; i < 4; i++) {
            int idx = tid + i * 256;
            int kk = idx >> 4;
            int cq = idx & 15;
            *(float4*)&Wsh[kk * 64 + cq * 4] = W4[(size_t)(kt * 64 + kk) * 16 + cq];
        }
        #pragma unroll
        for (int i = 0; i < 4; i++) {
            int idx = tid + i * 256;
            int row = idx >> 4;
            int kq = idx & 15;
            int n = base + row;
            float4 v = make_float4(0.f, 0.f, 0.f, 0.f);
            if (n < N) v = x4[(size_t)n * 32 + kt * 16 + kq];
            float* p = &xsh[row * 65 + kq * 4];
            p[0] = v.x; p[1] = v.y; p[2] = v.z; p[3] = v.w;
        }
        __syncthreads();

        #pragma unroll 16
        for (int k = 0; k < 64; k++) {
            float4 w = *(const float4*)&Wsh[k * 64 + cg * 4];
            float x0 = xsh[(rg * 4 + 0) * 65 + k];
            float x1 = xsh[(rg * 4 + 1) * 65 + k];
            float x2 = xsh[(rg * 4 + 2) * 65 + k];
            float x3 = xsh[(rg * 4 + 3) * 65 + k];
            a0.x += x0 * w.x; a0.y += x0 * w.y; a0.z += x0 * w.z; a0.w += x0 * w.w;
            a1.x += x1 * w.x; a1.y += x1 * w.y; a1.z += x1 * w.z; a1.w += x1 * w.w;
            a2.x += x2 * w.x; a2.y += x2 * w.y; a2.z += x2 * w.z; a2.w += x2 * w.w;
            a3.x += x3 * w.x; a3.y += x3 * w.y; a3.z += x3 * w.z; a3.w += x3 * w.w;
        }
    }

    int n0 = base + rg * 4;
    if (n0 + 0 < N) { float d = g_dis[n0 + 0];
        *(float4*)&g_m[(size_t)(n0 + 0) * 64 + cg * 4] = make_float4(a0.x * d, a0.y * d, a0.z * d, a0.w * d); }
    if (n0 + 1 < N) { float d = g_dis[n0 + 1];
        *(float4*)&g_m[(size_t)(n0 + 1) * 64 + cg * 4] = make_float4(a1.x * d, a1.y * d, a1.z * d, a1.w * d); }
    if (n0 + 2 < N) { float d = g_dis[n0 + 2];
        *(float4*)&g_m[(size_t)(n0 + 2) * 64 + cg * 4] = make_float4(a2.x * d, a2.y * d, a2.z * d, a2.w * d); }
    if (n0 + 3 < N) { float d = g_dis[n0 + 3];
        *(float4*)&g_m[(size_t)(n0 + 3) * 64 + cg * 4] = make_float4(a3.x * d, a3.y * d, a3.z * d, a3.w * d); }
}

// ---------------- gather layer 1: g_h = relu(dis*(sum+self)+b1) -----------
__global__ void k_gather1(const float* __restrict__ b1, int N) {
    int tid = threadIdx.x;
    int j = tid & 63;
    int n = blockIdx.x * 4 + (tid >> 6);
    if (n >= N) return;
    size_t s0 = (size_t)n * CAP;
    size_t s1 = s0 + g_cnt[n];
    float acc = 0.0f;
    for (size_t i = s0; i < s1; i++)
        acc += g_m[(size_t)g_srcs[i] * 64 + j];
    float v = g_dis[n] * (acc + g_m[(size_t)n * 64 + j]) + b1[j];
    g_h[(size_t)n * 64 + j] = fmaxf(v, 0.0f);
}

// ---------------- tab: tA = dis*(h.uA), tB = dis*(h.uB); warp per node ----
__global__ void k_tab(int N) {
    int gid = blockIdx.x * blockDim.x + threadIdx.x;
    int warp = gid >> 5;
    int lane = gid & 31;
    if (warp >= N) return;
    float h0 = g_h[(size_t)warp * 64 + lane];
    float h1 = g_h[(size_t)warp * 64 + lane + 32];
    float a = h0 * g_uA[lane] + h1 * g_uA[lane + 32];
    float b = h0 * g_uB[lane] + h1 * g_uB[lane + 32];
    #pragma unroll
    for (int o = 16; o; o >>= 1) {
        a += __shfl_down_sync(0xFFFFFFFFu, a, o);
        b += __shfl_down_sync(0xFFFFFFFFu, b, o);
    }
    if (lane == 0) {
        float dis = g_dis[warp];
        g_tab[warp] = make_float2(a * dis, b * dis);
    }
}

// ---------------- scalar gather 2: sA, sB; thread per node ----------------
__global__ void k_gather2s(int N) {
    int n = blockIdx.x * blockDim.x + threadIdx.x;
    if (n >= N) return;
    size_t s0 = (size_t)n * CAP;
    size_t s1 = s0 + g_cnt[n];
    float2 self = g_tab[n];
    float a = self.x, b = self.y;
    for (size_t i = s0; i < s1; i++) {
        float2 t = g_tab[g_srcs[i]];
        a += t.x; b += t.y;
    }
    float dis = g_dis[n];
    g_sA[n] = dis * a + g_cA;
    g_sB[n] = dis * b + g_cB;
}

// ---------------- edge kernel: 2 edges/thread, f32x2 packed FMAs ----------
__global__ __launch_bounds__(256) void k_edge(const float* __restrict__ ea_g,
                                              const int* __restrict__ src,
                                              const int* __restrict__ dst,
                                              const float* __restrict__ eW1,
                                              const float* __restrict__ eb1,
                                              float* __restrict__ out, int E) {
    __shared__ __align__(16) float shW[16 * 64];
    __shared__ __align__(16) float shB[64];
    __shared__ __align__(16) float shV[64];
    int tid = threadIdx.x;
    *(float4*)&shW[tid * 4] = ((const float4*)eW1)[tid];
    if (tid < 64) { shB[tid] = eb1[tid]; shV[tid] = g_v[tid]; }
    __syncthreads();

    int e0 = blockIdx.x * 512 + tid;
    int e1 = e0 + 256;
    bool ok0 = e0 < E;
    bool ok1 = e1 < E;

    // load edge features and pack each as {v, v} for f32x2 broadcast
    ull a0p[16];
    ull a1p[16];
    const float4* p0 = (const float4*)(ea_g + (size_t)e0 * 16);
    const float4* p1 = (const float4*)(ea_g + (size_t)e1 * 16);
    #pragma unroll
    for (int i = 0; i < 4; i++) {
        float4 t = ok0 ? p0[i] : make_float4(0.f, 0.f, 0.f, 0.f);
        a0p[i * 4 + 0] = pack2(t.x); a0p[i * 4 + 1] = pack2(t.y);
        a0p[i * 4 + 2] = pack2(t.z); a0p[i * 4 + 3] = pack2(t.w);
    }
    #pragma unroll
    for (int i = 0; i < 4; i++) {
        float4 t = ok1 ? p1[i] : make_float4(0.f, 0.f, 0.f, 0.f);
        a1p[i * 4 + 0] = pack2(t.x); a1p[i * 4 + 1] = pack2(t.y);
        a1p[i * 4 + 2] = pack2(t.z); a1p[i * 4 + 3] = pack2(t.w);
    }

    float score0 = 0.0f;
    float score1 = 0.0f;

    #pragma unroll 2
    for (int cb = 0; cb < 8; cb++) {
        ulonglong2 b01 = *(const ulonglong2*)&shB[cb * 8];
        ulonglong2 b23 = *(const ulonglong2*)&shB[cb * 8 + 4];
        ull accA0 = b01.x, accA1 = b01.y, accA2 = b23.x, accA3 = b23.y;
        ull accB0 = b01.x, accB1 = b01.y, accB2 = b23.x, accB3 = b23.y;
        #pragma unroll
        for (int k = 0; k < 16; k++) {
            ulonglong2 w01 = *(const ulonglong2*)&shW[k * 64 + cb * 8];
            ulonglong2 w23 = *(const ulonglong2*)&shW[k * 64 + cb * 8 + 4];
            accA0 = fma2(a0p[k], w01.x, accA0);
            accA1 = fma2(a0p[k], w01.y, accA1);
            accA2 = fma2(a0p[k], w23.x, accA2);
            accA3 = fma2(a0p[k], w23.y, accA3);
            accB0 = fma2(a1p[k], w01.x, accB0);
            accB1 = fma2(a1p[k], w01.y, accB1);
            accB2 = fma2(a1p[k], w23.x, accB2);
            accB3 = fma2(a1p[k], w23.y, accB3);
        }
        float4 v0 = *(const float4*)&shV[cb * 8];
        float4 v1 = *(const float4*)&shV[cb * 8 + 4];
        float lo, hi;
        unpack2(accA0, lo, hi); score0 += fmaxf(lo, 0.f) * v0.x + fmaxf(hi, 0.f) * v0.y;
        unpack2(accA1, lo, hi); score0 += fmaxf(lo, 0.f) * v0.z + fmaxf(hi, 0.f) * v0.w;
        unpack2(accA2, lo, hi); score0 += fmaxf(lo, 0.f) * v1.x + fmaxf(hi, 0.f) * v1.y;
        unpack2(accA3, lo, hi); score0 += fmaxf(lo, 0.f) * v1.z + fmaxf(hi, 0.f) * v1.w;
        unpack2(accB0, lo, hi); score1 += fmaxf(lo, 0.f) * v0.x + fmaxf(hi, 0.f) * v0.y;
        unpack2(accB1, lo, hi); score1 += fmaxf(lo, 0.f) * v0.z + fmaxf(hi, 0.f) * v0.w;
        unpack2(accB2, lo, hi); score1 += fmaxf(lo, 0.f) * v1.x + fmaxf(hi, 0.f) * v1.y;
        unpack2(accB3, lo, hi); score1 += fmaxf(lo, 0.f) * v1.z + fmaxf(hi, 0.f) * v1.w;
    }

    float c0 = g_c;
    if (ok0) out[e0] = score0 + c0 + g_sA[src[e0]] + g_sB[dst[e0]];
    if (ok1) out[e1] = score1 + c0 + g_sA[src[e1]] + g_sB[dst[e1]];
}

// ---------------- launch ----------------

extern "C" void kernel_launch(void* const* d_in, const int* in_sizes, int n_in,
                              void* d_out, int out_size) {
    const float* x        = (const float*)d_in[0];
    const int* ei         = (const int*)d_in[1];     // int32 (JAX canonicalizes int64)
    const float* ea       = (const float*)d_in[2];
    const float* W1       = (const float*)d_in[3];
    const float* b1       = (const float*)d_in[4];
    const float* W2       = (const float*)d_in[5];
    const float* b2       = (const float*)d_in[6];
    const float* eW1      = (const float*)d_in[7];
    const float* eb1      = (const float*)d_in[8];
    const float* eW2      = (const float*)d_in[9];
    const float* eb2      = (const float*)d_in[10];
    const float* fW       = (const float*)d_in[11];
    const float* fb       = (const float*)d_in[12];
    float* out            = (float*)d_out;

    int N = in_sizes[0] / 128;
    int E = in_sizes[2] / 16;
    const int* src = ei;
    const int* dst = ei + E;

    // bucket build
    k_zero<<<(N + 255) / 256, 256>>>(N);
    k_fill<<<(E + 255) / 256, 256>>>(src, dst, E);
    k_dis<<<(N + 255) / 256, 256>>>(N);
    k_prep<<<25, 256>>>(eW2, eb2, W2, b2, fW, fb);

    // layer 1
    k_gemm1<<<(N + 63) / 64, 256>>>(x, W1, N);
    k_gather1<<<(N + 3) / 4, 256>>>(b1, N);

    // layer 2 (folded): per-node scalars + scalar gather
    k_tab<<<((long long)N * 32 + 255) / 256, 256>>>(N);
    k_gather2s<<<(N + 255) / 256, 256>>>(N);

    // edge MLP + score
    k_edge<<<(E + 511) / 512, 256>>>(ea, src, dst, eW1, eb1, out, E);
}